// round 14
// baseline (speedup 1.0000x reference)
#include <cuda_runtime.h>
#include <cuda_fp16.h>
#include <math.h>
#include <stdint.h>

// ---------------- problem constants (fixed by reference) ----------------
#define NB    32
#define HH    32
#define WW    32
#define SEQ   1024          // H*W
#define DIMC  384
#define DIC   768           // 2*DIM
#define MLPD  1536          // 4*DIM
#define TOK   (NB*SEQ)      // 32768 tokens

// ---------------- scratch (device globals; no runtime alloc) ------------
__device__ __align__(16) __half g_xn [(size_t)TOK*DIMC];
__device__ __align__(16) __half g_xs [(size_t)TOK*DIMC];
__device__ __align__(16) __half g_hg [(size_t)TOK*3072];   // [tok][dir*1536+{hid,gate}]
__device__ __align__(16) __half g_e  [(size_t)TOK*1536];   // [tok][dir*768 + c]
__device__ float g_y  [(size_t)TOK*DIMC];
__device__ __align__(16) __half g_yn [(size_t)TOK*DIMC];
__device__ __align__(16) __half g_yh [(size_t)TOK*MLPD];
// transposed weights (K-major, [N][K]) for the B operand, fp16
__device__ __align__(16) __half g_wT  [(size_t)3072*DIMC];
__device__ __align__(16) __half g_oT  [(size_t)DIMC*1536]; // cols 0-767 o1^T, 768-1535 o2^T
__device__ __align__(16) __half g_p1T [(size_t)MLPD*DIMC];
__device__ __align__(16) __half g_p2T [(size_t)DIMC*MLPD];

// ================= small helpers ========================================
__device__ __forceinline__ uint32_t smem_to_u32(const void* p) {
    uint32_t a;
    asm("{ .reg .u64 t; cvta.to.shared.u64 t, %1; cvt.u32.u64 %0, t; }"
        : "=r"(a) : "l"(p));
    return a;
}
#define CP_ASYNC16(dst, src) \
    asm volatile("cp.async.cg.shared.global [%0], [%1], 16;" \
                 :: "r"(dst), "l"(src) : "memory")
#define CP_COMMIT() asm volatile("cp.async.commit_group;" ::: "memory")
#define CP_WAIT(n)  asm volatile("cp.async.wait_group %0;" :: "n"(n) : "memory")

// ldmatrix x4: four 8x8 b16 tiles; lanes 0-7/8-15/16-23/24-31 address tiles 0-3
#define LDSM_X4(r0,r1,r2,r3, addr)                                          \
    asm volatile("ldmatrix.sync.aligned.m8n8.x4.shared.b16 {%0,%1,%2,%3}, [%4];" \
        : "=r"(r0), "=r"(r1), "=r"(r2), "=r"(r3) : "r"(addr))

#define MMA_F16(d, a0,a1,a2,a3, b0,b1)                                      \
    asm volatile(                                                           \
        "mma.sync.aligned.m16n8k16.row.col.f32.f16.f16.f32 "                \
        "{%0,%1,%2,%3}, {%4,%5,%6,%7}, {%8,%9}, {%0,%1,%2,%3};\n"           \
        : "+f"(d[0]), "+f"(d[1]), "+f"(d[2]), "+f"(d[3])                    \
        : "r"(a0), "r"(a1), "r"(a2), "r"(a3), "r"(b0), "r"(b1))

// ---------------- layer norm: one warp per token row ---------------------
template<typename OT>
__global__ __launch_bounds__(256) void ln_kernel(
    const float* __restrict__ x, const float* __restrict__ gamma,
    const float* __restrict__ beta, OT* __restrict__ out, int rows)
{
    int gw   = (blockIdx.x * blockDim.x + threadIdx.x) >> 5;
    int lane = threadIdx.x & 31;
    if (gw >= rows) return;
    const float* xr = x + (size_t)gw * DIMC;
    float s = 0.f, s2 = 0.f;
    #pragma unroll
    for (int i = lane; i < DIMC; i += 32) { float v = xr[i]; s += v; s2 += v*v; }
    #pragma unroll
    for (int o = 16; o; o >>= 1) {
        s  += __shfl_xor_sync(0xffffffffu, s,  o);
        s2 += __shfl_xor_sync(0xffffffffu, s2, o);
    }
    float mu  = s * (1.f/DIMC);
    float var = s2 * (1.f/DIMC) - mu*mu;
    float inv = rsqrtf(var + 1e-5f);
    OT* orow = out + (size_t)gw * DIMC;
    #pragma unroll
    for (int i = lane; i < DIMC; i += 32)
        orow[i] = (OT)((xr[i] - mu) * inv * gamma[i] + beta[i]);
}

// ---------------- depthwise 3x3 conv, NHWC, pad=1; 4 ch/thread, fp16 in --
__global__ __launch_bounds__(256) void dwconv_kernel(
    const __half* __restrict__ xn, const float* __restrict__ w,
    const float* __restrict__ b, __half* __restrict__ xs)
{
    int idx = blockIdx.x * blockDim.x + threadIdx.x;   // 0 .. TOK*DIMC/4-1
    if (idx >= TOK*(DIMC/4)) return;
    int c4 = idx % (DIMC/4);
    int p  = idx / (DIMC/4);
    int c  = c4 * 4;
    int xq = p % WW;
    int yq = (p / WW) % HH;
    int n  = p / SEQ;

    float4 bb = *(const float4*)(b + c);
    float a0 = bb.x, a1 = bb.y, a2 = bb.z, a3 = bb.w;
    const float* w0 = w + (c+0)*9;
    const float* w1 = w + (c+1)*9;
    const float* w2 = w + (c+2)*9;
    const float* w3 = w + (c+3)*9;

    #pragma unroll
    for (int ky = 0; ky < 3; ky++) {
        int yy = yq + ky - 1;
        if (yy < 0 || yy >= HH) continue;
        #pragma unroll
        for (int kx = 0; kx < 3; kx++) {
            int xx = xq + kx - 1;
            if (xx < 0 || xx >= WW) continue;
            uint2 pk = *(const uint2*)(xn + ((size_t)n*SEQ + yy*WW + xx)*DIMC + c);
            float2 f01 = __half22float2(*(__half2*)&pk.x);
            float2 f23 = __half22float2(*(__half2*)&pk.y);
            int t = ky*3 + kx;
            a0 = fmaf(w0[t], f01.x, a0);
            a1 = fmaf(w1[t], f01.y, a1);
            a2 = fmaf(w2[t], f23.x, a2);
            a3 = fmaf(w3[t], f23.y, a3);
        }
    }
    __half2 h01 = __floats2half2_rn(a0, a1);
    __half2 h23 = __floats2half2_rn(a2, a3);
    uint2 pk;
    pk.x = *(uint32_t*)&h01;
    pk.y = *(uint32_t*)&h23;
    *(uint2*)(xs + (size_t)p*DIMC + c) = pk;
}

// ---------------- all 6 weight transposes [K,N]->fp16 [N,K(stride)] ------
struct TransParams {
    const float* in[6];
    __half*      out[6];
    int K[6], N[6], ostr[6];
};
__global__ __launch_bounds__(256) void transpose_all_kernel(TransParams tp)
{
    int id = blockIdx.z;
    int K = tp.K[id], N = tp.N[id], ostr = tp.ostr[id];
    int kb = blockIdx.x * 32, nb = blockIdx.y * 32;
    if (kb >= K || nb >= N) return;
    const float* in = tp.in[id];
    __half* out = tp.out[id];
    __shared__ float t[32][33];
    int tx = threadIdx.x & 31, ty = threadIdx.x >> 5;   // 32 x 8
    #pragma unroll
    for (int i = 0; i < 32; i += 8)
        t[ty+i][tx] = in[(size_t)(kb+ty+i)*N + nb+tx];
    __syncthreads();
    #pragma unroll
    for (int i = 0; i < 32; i += 8)
        out[(size_t)(nb+ty+i)*ostr + kb+tx] = __float2half(t[tx][ty+i]);
}

// ---------------- fp16 tensor GEMM, occupancy-3, swizzled smem -----------
// C[M,N] = act(A[M,K] @ Bt[N,K]^T + bias) + add.  ACT: 0=none, 1=exact GELU.
// CTA: 128 threads, tile 128(M) x 64(N), K-tile 64. 4 warps as 2(m) x 2(n);
// warp tile 64 x 32. XOR-swizzled smem (no pad) -> 73728 B/CTA -> 3 CTAs/SM.
#define STAGES 3
#define AROWS  128
#define BROWS  64
#define ABYTES (AROWS*128)         // 16384
#define BBYTES (BROWS*128)         // 8192
#define STB    (ABYTES+BBYTES)     // 24576
#define GSMEM  (STAGES*STB)        // 73728

template<int ACT, typename CT>
__global__ __launch_bounds__(128, 3) void tc_gemm(
    const __half* __restrict__ A, const __half* __restrict__ Bt,
    const float* __restrict__ bias, const float* __restrict__ addp,
    CT* __restrict__ C, int M, int N, int K)
{
    extern __shared__ char smem[];
    const uint32_t sbase = smem_to_u32(smem);

    const int tid  = threadIdx.x;
    const int wid  = tid >> 5;
    const int lane = tid & 31;
    const int wm   = wid & 1;                // warp m (2) -> 64 rows
    const int wn   = wid >> 1;               // warp n (2) -> 32 cols
    const int gid  = lane >> 2;              // 0..7
    const int tig  = lane & 3;               // 0..3
    const int m0   = blockIdx.y * 128;
    const int n0   = blockIdx.x * 64;
    const int nk   = K >> 6;                 // 64-k tiles

    // ldmatrix per-lane addressing (tile-quad q = lane>>3, row-in-tile lane&7)
    const int rowin = lane & 7;
    const int q     = lane >> 3;
    const int qa    = q >> 1;                // A k-chunk select
    const int qb    = q & 1;                 // B k-chunk select
    uint32_t aoff[4], boff[2];
    #pragma unroll
    for (int mi = 0; mi < 4; mi++)
        aoff[mi] = (uint32_t)((wm*64 + mi*16 + (q & 1)*8 + rowin) * 128);
    #pragma unroll
    for (int j = 0; j < 2; j++)
        boff[j] = (uint32_t)((wn*32 + j*16 + (q >> 1)*8 + rowin) * 128);

    float acc[4][4][4];
    #pragma unroll
    for (int mi = 0; mi < 4; mi++)
        #pragma unroll
        for (int ni = 0; ni < 4; ni++)
            #pragma unroll
            for (int p = 0; p < 4; p++) acc[mi][ni][p] = 0.f;

    // ---- tile loader: global -> swizzled smem stage (16B chunks) ---------
    auto load_tile = [&](int i) {
        uint32_t sa = sbase + (i % STAGES) * STB;
        uint32_t sb = sa + ABYTES;
        const __half* Ag = A  + (size_t)m0 * K + i*64;
        const __half* Bg = Bt + (size_t)n0 * K + i*64;
        #pragma unroll
        for (int t = 0; t < 8; t++) {                 // A: 1024 chunks
            int f = tid + t*128;
            int r = f >> 3, kc = f & 7;
            CP_ASYNC16(sa + r*128 + ((kc ^ (r & 7)) << 4), Ag + (size_t)r*K + kc*8);
        }
        #pragma unroll
        for (int t = 0; t < 4; t++) {                 // B: 512 chunks
            int f = tid + t*128;
            int r = f >> 3, kc = f & 7;
            CP_ASYNC16(sb + r*128 + ((kc ^ (r & 7)) << 4), Bg + (size_t)r*K + kc*8);
        }
    };

    load_tile(0); CP_COMMIT();
    load_tile(1); CP_COMMIT();

    uint32_t af[2][4][4];
    uint32_t bf[2][4][2];

    for (int i = 0; i < nk; i++) {
        CP_WAIT(1);
        __syncthreads();
        if (i + 2 < nk) load_tile(i + 2);
        CP_COMMIT();

        uint32_t sa = sbase + (i % STAGES) * STB;
        uint32_t sb = sa + ABYTES;

        // prefetch ks=0 fragments into buffer 0 (4 A + 2 B ldmatrix.x4)
        {
            uint32_t ca = (uint32_t)((qa ^ rowin) << 4);
            uint32_t cb = (uint32_t)((qb ^ rowin) << 4);
            #pragma unroll
            for (int mi = 0; mi < 4; mi++)
                LDSM_X4(af[0][mi][0], af[0][mi][1], af[0][mi][2], af[0][mi][3],
                        sa + aoff[mi] + ca);
            #pragma unroll
            for (int j = 0; j < 2; j++)
                LDSM_X4(bf[0][2*j][0], bf[0][2*j][1], bf[0][2*j+1][0], bf[0][2*j+1][1],
                        sb + boff[j] + cb);
        }

        #pragma unroll
        for (int ks = 0; ks < 4; ks++) {
            int cur = ks & 1, nxt = cur ^ 1;
            if (ks < 3) {
                uint32_t ca = (uint32_t)(((2*(ks+1) + qa) ^ rowin) << 4);
                uint32_t cb = (uint32_t)(((2*(ks+1) + qb) ^ rowin) << 4);
                #pragma unroll
                for (int mi = 0; mi < 4; mi++)
                    LDSM_X4(af[nxt][mi][0], af[nxt][mi][1], af[nxt][mi][2], af[nxt][mi][3],
                            sa + aoff[mi] + ca);
                #pragma unroll
                for (int j = 0; j < 2; j++)
                    LDSM_X4(bf[nxt][2*j][0], bf[nxt][2*j][1], bf[nxt][2*j+1][0], bf[nxt][2*j+1][1],
                            sb + boff[j] + cb);
            }
            #pragma unroll
            for (int mi = 0; mi < 4; mi++)
                #pragma unroll
                for (int ni = 0; ni < 4; ni++)
                    MMA_F16(acc[mi][ni],
                            af[cur][mi][0], af[cur][mi][1], af[cur][mi][2], af[cur][mi][3],
                            bf[cur][ni][0], bf[cur][ni][1]);
        }
    }

    // ---- epilogue ---------------------------------------------------------
    #pragma unroll
    for (int mi = 0; mi < 4; mi++) {
        int r0 = m0 + wm*64 + mi*16 + gid;
        #pragma unroll
        for (int ni = 0; ni < 4; ni++) {
            int cn = n0 + wn*32 + ni*8 + tig*2;
            #pragma unroll
            for (int half = 0; half < 2; half++) {
                int r = r0 + half*8;
                float v0 = acc[mi][ni][half*2+0];
                float v1 = acc[mi][ni][half*2+1];
                if (bias) { v0 += bias[cn]; v1 += bias[cn+1]; }
                if (ACT == 1) {
                    v0 = 0.5f * v0 * (1.f + erff(v0 * 0.70710678118654752f));
                    v1 = 0.5f * v1 * (1.f + erff(v1 * 0.70710678118654752f));
                }
                if (addp) {
                    float2 ad = *(const float2*)(addp + (size_t)r*N + cn);
                    v0 += ad.x; v1 += ad.y;
                }
                if (sizeof(CT) == 2) {
                    __half2 hv = __floats2half2_rn(v0, v1);
                    *(__half2*)((__half*)C + (size_t)r*N + cn) = hv;
                } else {
                    float2 ov; ov.x = v0; ov.y = v1;
                    *(float2*)((float*)C + (size_t)r*N + cn) = ov;
                }
            }
        }
    }
}

// ---------------- minGRU scans, LINEAR domain, 2 channels/thread ---------
// h_t = sigmoid(-gate)*h_{t-1} + sigmoid(gate)*g(hid),
// g(x) = x>=0 ? x+0.5 : sigmoid(x).
// Each thread owns channels (2c, 2c+1): hid/gate/e pairs are contiguous ->
// LDG.32/STG.32 per pair, warps touch full 128B sectors. 64-thr CTAs to
// minimize wave quantization (384 CTAs over 148 SMs).
__global__ __launch_bounds__(64) void scan_kernel(
    const __half* __restrict__ hg, __half* __restrict__ e)
{
    int idx = blockIdx.x * 64 + threadIdx.x;   // 0 .. 2*NB*384-1
    int dir = idx / (NB*(DIC/2));
    int r   = idx % (NB*(DIC/2));
    int n   = r / (DIC/2);
    int c   = (r % (DIC/2)) * 2;
    const int coff  = dir * 1536 + c;                  // hid pair; gate at +768
    const int eoff  = dir * 768 + c;
    const size_t base  = (size_t)n * SEQ * 3072;
    const size_t ebase = (size_t)n * SEQ * 1536;

    float h0 = 0.f, h1 = 0.f;
    int t0  = dir ? SEQ-1 : 0;
    int dt  = dir ? -1 : 1;
    #pragma unroll 2
    for (int s = 0; s < SEQ; s++) {
        int t = t0 + s*dt;
        size_t row = base + (size_t)t * 3072;
        uint32_t hid2u = *(const uint32_t*)(hg + row + coff);
        uint32_t gat2u = *(const uint32_t*)(hg + row + coff + 768);
        float2 hid = __half22float2(*(__half2*)&hid2u);
        float2 gat = __half22float2(*(__half2*)&gat2u);

        float cs0 = __fdividef(1.f, 1.f + __expf(gat.x));      // sigmoid(-gate)
        float cs1 = __fdividef(1.f, 1.f + __expf(gat.y));
        float g0  = (hid.x >= 0.f) ? (hid.x + 0.5f)
                                   : __fdividef(1.f, 1.f + __expf(-hid.x));
        float g1  = (hid.y >= 0.f) ? (hid.y + 0.5f)
                                   : __fdividef(1.f, 1.f + __expf(-hid.y));
        h0 = fmaf(cs0, h0, (1.f - cs0) * g0);
        h1 = fmaf(cs1, h1, (1.f - cs1) * g1);

        __half2 hv = __floats2half2_rn(h0, h1);
        *(__half2*)(e + ebase + (size_t)t*1536 + eoff) = hv;
    }
}

// ---------------- launch -------------------------------------------------
extern "C" void kernel_launch(void* const* d_in, const int* in_sizes, int n_in,
                              void* d_out, int out_size)
{
    const float* x        = (const float*)d_in[0];
    const float* gamma1   = (const float*)d_in[1];
    const float* beta1    = (const float*)d_in[2];
    const float* dwc_w    = (const float*)d_in[3];
    const float* dwc_b    = (const float*)d_in[4];
    const float* gru1_w   = (const float*)d_in[5];
    const float* gru1_out = (const float*)d_in[6];
    const float* gru2_w   = (const float*)d_in[7];
    const float* gru2_out = (const float*)d_in[8];
    const float* gamma2   = (const float*)d_in[9];
    const float* beta2    = (const float*)d_in[10];
    const float* p1_w     = (const float*)d_in[11];
    const float* p1_b     = (const float*)d_in[12];
    const float* p2_w     = (const float*)d_in[13];
    const float* p2_b     = (const float*)d_in[14];
    float* out = (float*)d_out;

    float *y;
    __half *xn, *xs, *hg, *e, *yn, *yh, *wT, *oT, *p1T, *p2T;
    cudaGetSymbolAddress((void**)&xn,  g_xn);
    cudaGetSymbolAddress((void**)&xs,  g_xs);
    cudaGetSymbolAddress((void**)&hg,  g_hg);
    cudaGetSymbolAddress((void**)&e,   g_e);
    cudaGetSymbolAddress((void**)&y,   g_y);
    cudaGetSymbolAddress((void**)&yn,  g_yn);
    cudaGetSymbolAddress((void**)&yh,  g_yh);
    cudaGetSymbolAddress((void**)&wT,  g_wT);
    cudaGetSymbolAddress((void**)&oT,  g_oT);
    cudaGetSymbolAddress((void**)&p1T, g_p1T);
    cudaGetSymbolAddress((void**)&p2T, g_p2T);

    cudaFuncSetAttribute(tc_gemm<0,float>,  cudaFuncAttributeMaxDynamicSharedMemorySize, GSMEM);
    cudaFuncSetAttribute(tc_gemm<0,__half>, cudaFuncAttributeMaxDynamicSharedMemorySize, GSMEM);
    cudaFuncSetAttribute(tc_gemm<1,__half>, cudaFuncAttributeMaxDynamicSharedMemorySize, GSMEM);

    // 0. all weight transposes in one launch (K-major fp16 B operands)
    {
        TransParams tp;
        tp.in[0]=gru1_w;   tp.out[0]=wT;                      tp.K[0]=DIMC; tp.N[0]=2*DIC; tp.ostr[0]=DIMC;
        tp.in[1]=gru2_w;   tp.out[1]=wT+(size_t)1536*DIMC;    tp.K[1]=DIMC; tp.N[1]=2*DIC; tp.ostr[1]=DIMC;
        tp.in[2]=gru1_out; tp.out[2]=oT;                      tp.K[2]=DIC;  tp.N[2]=DIMC;  tp.ostr[2]=1536;
        tp.in[3]=gru2_out; tp.out[3]=oT+768;                  tp.K[3]=DIC;  tp.N[3]=DIMC;  tp.ostr[3]=1536;
        tp.in[4]=p1_w;     tp.out[4]=p1T;                     tp.K[4]=DIMC; tp.N[4]=MLPD;  tp.ostr[4]=DIMC;
        tp.in[5]=p2_w;     tp.out[5]=p2T;                     tp.K[5]=MLPD; tp.N[5]=DIMC;  tp.ostr[5]=MLPD;
        transpose_all_kernel<<<dim3(48, 48, 6), 256>>>(tp);
    }
    // 1. LN1 (fp16 out -> conv input)
    ln_kernel<__half><<<(TOK*32 + 255)/256, 256>>>(x, gamma1, beta1, xn, TOK);
    // 2. depthwise conv 3x3 (fp16 in/out, 4 ch/thread)
    dwconv_kernel<<<(TOK*(DIMC/4) + 255)/256, 256>>>(xn, dwc_w, dwc_b, xs);
    // 3. fused GRU input projections: hg = xs @ [W1|W2]  (N=3072, K=384), fp16 out
    tc_gemm<0,__half><<<dim3(3072/64, TOK/128), 128, GSMEM>>>(
        xs, wT, nullptr, nullptr, hg, TOK, 3072, DIMC);
    // 4. forward + backward minGRU scans (linear, coalesced) -> e[tok][1536]
    scan_kernel<<<(2*NB*(DIC/2))/64, 64>>>(hg, e);
    // 5. fused output projections + residual: y = e @ [O1;O2] + x  (K=1536), f32
    tc_gemm<0,float><<<dim3(DIMC/64, TOK/128), 128, GSMEM>>>(
        e, oT, nullptr, x, y, TOK, DIMC, 1536);
    // 6. LN2 (fp16 out)
    ln_kernel<__half><<<(TOK*32 + 255)/256, 256>>>(y, gamma2, beta2, yn, TOK);
    // 7. MLP up + exact GELU (fp16 out)
    tc_gemm<1,__half><<<dim3(MLPD/64, TOK/128), 128, GSMEM>>>(
        yn, p1T, p1_b, nullptr, yh, TOK, MLPD, DIMC);
    // 8. MLP down + bias + residual -> out (f32)
    tc_gemm<0,float><<<dim3(DIMC/64, TOK/128), 128, GSMEM>>>(
        yh, p2T, p2_b, y, out, TOK, DIMC, MLPD);
}

// round 16
// speedup vs baseline: 1.2484x; 1.2484x over previous
#include <cuda_runtime.h>
#include <cuda_fp16.h>
#include <math.h>
#include <stdint.h>

// ---------------- problem constants (fixed by reference) ----------------
#define NB    32
#define HH    32
#define WW    32
#define SEQ   1024          // H*W
#define DIMC  384
#define DIC   768           // 2*DIM
#define MLPD  1536          // 4*DIM
#define TOK   (NB*SEQ)      // 32768 tokens

// ---------------- scratch (device globals; no runtime alloc) ------------
__device__ __align__(16) __half g_xn [(size_t)TOK*DIMC];
__device__ __align__(16) __half g_xs [(size_t)TOK*DIMC];
__device__ __align__(16) __half g_hg [(size_t)TOK*3072];   // [tok][dir*1536+{hid,gate}]
__device__ __align__(16) __half g_e  [(size_t)TOK*1536];   // [tok][dir*768 + c]
__device__ float g_y  [(size_t)TOK*DIMC];
__device__ __align__(16) __half g_yn [(size_t)TOK*DIMC];
__device__ __align__(16) __half g_yh [(size_t)TOK*MLPD];
// transposed weights (K-major, [N][K]) for the B operand, fp16
__device__ __align__(16) __half g_wT  [(size_t)3072*DIMC];
__device__ __align__(16) __half g_oT  [(size_t)DIMC*1536]; // cols 0-767 o1^T, 768-1535 o2^T
__device__ __align__(16) __half g_p1T [(size_t)MLPD*DIMC];
__device__ __align__(16) __half g_p2T [(size_t)DIMC*MLPD];

// ================= small helpers ========================================
__device__ __forceinline__ uint32_t smem_to_u32(const void* p) {
    uint32_t a;
    asm("{ .reg .u64 t; cvta.to.shared.u64 t, %1; cvt.u32.u64 %0, t; }"
        : "=r"(a) : "l"(p));
    return a;
}
#define CP_ASYNC16(dst, src) \
    asm volatile("cp.async.cg.shared.global [%0], [%1], 16;" \
                 :: "r"(dst), "l"(src) : "memory")
#define CP_COMMIT() asm volatile("cp.async.commit_group;" ::: "memory")
#define CP_WAIT(n)  asm volatile("cp.async.wait_group %0;" :: "n"(n) : "memory")

// ldmatrix x4: four 8x8 b16 tiles; lanes 0-7/8-15/16-23/24-31 address tiles 0-3
#define LDSM_X4(r0,r1,r2,r3, addr)                                          \
    asm volatile("ldmatrix.sync.aligned.m8n8.x4.shared.b16 {%0,%1,%2,%3}, [%4];" \
        : "=r"(r0), "=r"(r1), "=r"(r2), "=r"(r3) : "r"(addr))

#define MMA_F16(d, a0,a1,a2,a3, b0,b1)                                      \
    asm volatile(                                                           \
        "mma.sync.aligned.m16n8k16.row.col.f32.f16.f16.f32 "                \
        "{%0,%1,%2,%3}, {%4,%5,%6,%7}, {%8,%9}, {%0,%1,%2,%3};\n"           \
        : "+f"(d[0]), "+f"(d[1]), "+f"(d[2]), "+f"(d[3])                    \
        : "r"(a0), "r"(a1), "r"(a2), "r"(a3), "r"(b0), "r"(b1))

// ---------------- layer norm: one warp per token row ---------------------
template<typename OT>
__global__ __launch_bounds__(256) void ln_kernel(
    const float* __restrict__ x, const float* __restrict__ gamma,
    const float* __restrict__ beta, OT* __restrict__ out, int rows)
{
    int gw   = (blockIdx.x * blockDim.x + threadIdx.x) >> 5;
    int lane = threadIdx.x & 31;
    if (gw >= rows) return;
    const float* xr = x + (size_t)gw * DIMC;
    float s = 0.f, s2 = 0.f;
    #pragma unroll
    for (int i = lane; i < DIMC; i += 32) { float v = xr[i]; s += v; s2 += v*v; }
    #pragma unroll
    for (int o = 16; o; o >>= 1) {
        s  += __shfl_xor_sync(0xffffffffu, s,  o);
        s2 += __shfl_xor_sync(0xffffffffu, s2, o);
    }
    float mu  = s * (1.f/DIMC);
    float var = s2 * (1.f/DIMC) - mu*mu;
    float inv = rsqrtf(var + 1e-5f);
    OT* orow = out + (size_t)gw * DIMC;
    #pragma unroll
    for (int i = lane; i < DIMC; i += 32)
        orow[i] = (OT)((xr[i] - mu) * inv * gamma[i] + beta[i]);
}

// ---------------- depthwise 3x3 conv, NHWC, pad=1; 4 ch/thread, fp16 in --
__global__ __launch_bounds__(256) void dwconv_kernel(
    const __half* __restrict__ xn, const float* __restrict__ w,
    const float* __restrict__ b, __half* __restrict__ xs)
{
    int idx = blockIdx.x * blockDim.x + threadIdx.x;   // 0 .. TOK*DIMC/4-1
    if (idx >= TOK*(DIMC/4)) return;
    int c4 = idx % (DIMC/4);
    int p  = idx / (DIMC/4);
    int c  = c4 * 4;
    int xq = p % WW;
    int yq = (p / WW) % HH;
    int n  = p / SEQ;

    float4 bb = *(const float4*)(b + c);
    float a0 = bb.x, a1 = bb.y, a2 = bb.z, a3 = bb.w;
    const float* w0 = w + (c+0)*9;
    const float* w1 = w + (c+1)*9;
    const float* w2 = w + (c+2)*9;
    const float* w3 = w + (c+3)*9;

    #pragma unroll
    for (int ky = 0; ky < 3; ky++) {
        int yy = yq + ky - 1;
        if (yy < 0 || yy >= HH) continue;
        #pragma unroll
        for (int kx = 0; kx < 3; kx++) {
            int xx = xq + kx - 1;
            if (xx < 0 || xx >= WW) continue;
            uint2 pk = *(const uint2*)(xn + ((size_t)n*SEQ + yy*WW + xx)*DIMC + c);
            float2 f01 = __half22float2(*(__half2*)&pk.x);
            float2 f23 = __half22float2(*(__half2*)&pk.y);
            int t = ky*3 + kx;
            a0 = fmaf(w0[t], f01.x, a0);
            a1 = fmaf(w1[t], f01.y, a1);
            a2 = fmaf(w2[t], f23.x, a2);
            a3 = fmaf(w3[t], f23.y, a3);
        }
    }
    __half2 h01 = __floats2half2_rn(a0, a1);
    __half2 h23 = __floats2half2_rn(a2, a3);
    uint2 pk;
    pk.x = *(uint32_t*)&h01;
    pk.y = *(uint32_t*)&h23;
    *(uint2*)(xs + (size_t)p*DIMC + c) = pk;
}

// ---------------- all 6 weight transposes [K,N]->fp16 [N,K(stride)] ------
struct TransParams {
    const float* in[6];
    __half*      out[6];
    int K[6], N[6], ostr[6];
};
__global__ __launch_bounds__(256) void transpose_all_kernel(TransParams tp)
{
    int id = blockIdx.z;
    int K = tp.K[id], N = tp.N[id], ostr = tp.ostr[id];
    int kb = blockIdx.x * 32, nb = blockIdx.y * 32;
    if (kb >= K || nb >= N) return;
    const float* in = tp.in[id];
    __half* out = tp.out[id];
    __shared__ float t[32][33];
    int tx = threadIdx.x & 31, ty = threadIdx.x >> 5;   // 32 x 8
    #pragma unroll
    for (int i = 0; i < 32; i += 8)
        t[ty+i][tx] = in[(size_t)(kb+ty+i)*N + nb+tx];
    __syncthreads();
    #pragma unroll
    for (int i = 0; i < 32; i += 8)
        out[(size_t)(nb+ty+i)*ostr + kb+tx] = __float2half(t[tx][ty+i]);
}

// ---------------- fp16 tensor GEMM, occupancy-3, swizzled smem -----------
// C[M,N] = act(A[M,K] @ Bt[N,K]^T + bias) + add.  ACT: 0=none, 1=exact GELU.
// CTA: 128 threads, tile 128(M) x 64(N), K-tile 64. 4 warps as 2(m) x 2(n);
// warp tile 64 x 32. XOR-swizzled smem (no pad) -> 73728 B/CTA -> 3 CTAs/SM.
#define STAGES 3
#define AROWS  128
#define BROWS  64
#define ABYTES (AROWS*128)         // 16384
#define BBYTES (BROWS*128)         // 8192
#define STB    (ABYTES+BBYTES)     // 24576
#define GSMEM  (STAGES*STB)        // 73728

template<int ACT, typename CT>
__global__ __launch_bounds__(128, 3) void tc_gemm(
    const __half* __restrict__ A, const __half* __restrict__ Bt,
    const float* __restrict__ bias, const float* __restrict__ addp,
    CT* __restrict__ C, int M, int N, int K)
{
    extern __shared__ char smem[];
    const uint32_t sbase = smem_to_u32(smem);

    const int tid  = threadIdx.x;
    const int wid  = tid >> 5;
    const int lane = tid & 31;
    const int wm   = wid & 1;                // warp m (2) -> 64 rows
    const int wn   = wid >> 1;               // warp n (2) -> 32 cols
    const int gid  = lane >> 2;              // 0..7
    const int tig  = lane & 3;               // 0..3
    const int m0   = blockIdx.y * 128;
    const int n0   = blockIdx.x * 64;
    const int nk   = K >> 6;                 // 64-k tiles

    // ldmatrix per-lane addressing (tile-quad q = lane>>3, row-in-tile lane&7)
    const int rowin = lane & 7;
    const int q     = lane >> 3;
    const int qa    = q >> 1;                // A k-chunk select
    const int qb    = q & 1;                 // B k-chunk select
    uint32_t aoff[4], boff[2];
    #pragma unroll
    for (int mi = 0; mi < 4; mi++)
        aoff[mi] = (uint32_t)((wm*64 + mi*16 + (q & 1)*8 + rowin) * 128);
    #pragma unroll
    for (int j = 0; j < 2; j++)
        boff[j] = (uint32_t)((wn*32 + j*16 + (q >> 1)*8 + rowin) * 128);

    float acc[4][4][4];
    #pragma unroll
    for (int mi = 0; mi < 4; mi++)
        #pragma unroll
        for (int ni = 0; ni < 4; ni++)
            #pragma unroll
            for (int p = 0; p < 4; p++) acc[mi][ni][p] = 0.f;

    // ---- tile loader: global -> swizzled smem stage (16B chunks) ---------
    auto load_tile = [&](int i) {
        uint32_t sa = sbase + (i % STAGES) * STB;
        uint32_t sb = sa + ABYTES;
        const __half* Ag = A  + (size_t)m0 * K + i*64;
        const __half* Bg = Bt + (size_t)n0 * K + i*64;
        #pragma unroll
        for (int t = 0; t < 8; t++) {                 // A: 1024 chunks
            int f = tid + t*128;
            int r = f >> 3, kc = f & 7;
            CP_ASYNC16(sa + r*128 + ((kc ^ (r & 7)) << 4), Ag + (size_t)r*K + kc*8);
        }
        #pragma unroll
        for (int t = 0; t < 4; t++) {                 // B: 512 chunks
            int f = tid + t*128;
            int r = f >> 3, kc = f & 7;
            CP_ASYNC16(sb + r*128 + ((kc ^ (r & 7)) << 4), Bg + (size_t)r*K + kc*8);
        }
    };

    load_tile(0); CP_COMMIT();
    load_tile(1); CP_COMMIT();

    uint32_t af[2][4][4];
    uint32_t bf[2][4][2];

    for (int i = 0; i < nk; i++) {
        CP_WAIT(1);
        __syncthreads();
        if (i + 2 < nk) load_tile(i + 2);
        CP_COMMIT();

        uint32_t sa = sbase + (i % STAGES) * STB;
        uint32_t sb = sa + ABYTES;

        // prefetch ks=0 fragments into buffer 0 (4 A + 2 B ldmatrix.x4)
        {
            uint32_t ca = (uint32_t)((qa ^ rowin) << 4);
            uint32_t cb = (uint32_t)((qb ^ rowin) << 4);
            #pragma unroll
            for (int mi = 0; mi < 4; mi++)
                LDSM_X4(af[0][mi][0], af[0][mi][1], af[0][mi][2], af[0][mi][3],
                        sa + aoff[mi] + ca);
            #pragma unroll
            for (int j = 0; j < 2; j++)
                LDSM_X4(bf[0][2*j][0], bf[0][2*j][1], bf[0][2*j+1][0], bf[0][2*j+1][1],
                        sb + boff[j] + cb);
        }

        #pragma unroll
        for (int ks = 0; ks < 4; ks++) {
            int cur = ks & 1, nxt = cur ^ 1;
            if (ks < 3) {
                uint32_t ca = (uint32_t)(((2*(ks+1) + qa) ^ rowin) << 4);
                uint32_t cb = (uint32_t)(((2*(ks+1) + qb) ^ rowin) << 4);
                #pragma unroll
                for (int mi = 0; mi < 4; mi++)
                    LDSM_X4(af[nxt][mi][0], af[nxt][mi][1], af[nxt][mi][2], af[nxt][mi][3],
                            sa + aoff[mi] + ca);
                #pragma unroll
                for (int j = 0; j < 2; j++)
                    LDSM_X4(bf[nxt][2*j][0], bf[nxt][2*j][1], bf[nxt][2*j+1][0], bf[nxt][2*j+1][1],
                            sb + boff[j] + cb);
            }
            #pragma unroll
            for (int mi = 0; mi < 4; mi++)
                #pragma unroll
                for (int ni = 0; ni < 4; ni++)
                    MMA_F16(acc[mi][ni],
                            af[cur][mi][0], af[cur][mi][1], af[cur][mi][2], af[cur][mi][3],
                            bf[cur][ni][0], bf[cur][ni][1]);
        }
    }

    // ---- epilogue ---------------------------------------------------------
    #pragma unroll
    for (int mi = 0; mi < 4; mi++) {
        int r0 = m0 + wm*64 + mi*16 + gid;
        #pragma unroll
        for (int ni = 0; ni < 4; ni++) {
            int cn = n0 + wn*32 + ni*8 + tig*2;
            #pragma unroll
            for (int half = 0; half < 2; half++) {
                int r = r0 + half*8;
                float v0 = acc[mi][ni][half*2+0];
                float v1 = acc[mi][ni][half*2+1];
                if (bias) { v0 += bias[cn]; v1 += bias[cn+1]; }
                if (ACT == 1) {
                    v0 = 0.5f * v0 * (1.f + erff(v0 * 0.70710678118654752f));
                    v1 = 0.5f * v1 * (1.f + erff(v1 * 0.70710678118654752f));
                }
                if (addp) {
                    float2 ad = *(const float2*)(addp + (size_t)r*N + cn);
                    v0 += ad.x; v1 += ad.y;
                }
                if (sizeof(CT) == 2) {
                    __half2 hv = __floats2half2_rn(v0, v1);
                    *(__half2*)((__half*)C + (size_t)r*N + cn) = hv;
                } else {
                    float2 ov; ov.x = v0; ov.y = v1;
                    *(float2*)((float*)C + (size_t)r*N + cn) = ov;
                }
            }
        }
    }
}

// ---------------- minGRU scans: chunked affine scan, 8x time-parallel ----
// h_t = a_t*h + b_t with a = sigmoid(-gate), b = (1-a)*g(hid),
// g(x) = x>=0 ? x+0.5 : sigmoid(x).
// CTA (256 thr) owns 32 chains x 8 chunks of 128 steps; warp j = chunk j,
// lane = chain (32 consecutive channels -> 64B coalesced accesses).
// Phase 1: per-thread local affine composition (A,B). Phase 2: 8-step
// per-chain prefix (warp 0). Phase 3: replay from h_init, write e.
#define CHUNK 128
#define NCHUNK 8

__device__ __forceinline__ void scan_ab(float hid, float gate, float& a, float& b)
{
    a = __fdividef(1.f, 1.f + __expf(gate));          // sigmoid(-gate)
    float g = (hid >= 0.f) ? (hid + 0.5f)
                           : __fdividef(1.f, 1.f + __expf(-hid));
    b = (1.f - a) * g;
}

__global__ __launch_bounds__(256) void scan_kernel(
    const __half* __restrict__ hg, __half* __restrict__ e)
{
    __shared__ float As[NCHUNK][32], Bs[NCHUNK][32], Hs[NCHUNK][32];

    int bid  = blockIdx.x;                 // 0 .. 2*NB*24-1
    int dir  = bid / (NB*(DIC/32));
    int r    = bid % (NB*(DIC/32));
    int n    = r / (DIC/32);
    int c    = (r % (DIC/32)) * 32 + (threadIdx.x & 31);
    int j    = threadIdx.x >> 5;           // chunk 0..7
    const int coff = dir * 1536 + c;       // hid col; gate at +768
    const int eoff = dir * 768 + c;
    const size_t base  = (size_t)n * SEQ * 3072;
    const size_t ebase = (size_t)n * SEQ * 1536;
    const int lane = threadIdx.x & 31;

    // Phase 1: local composition over s in [j*CHUNK, (j+1)*CHUNK)
    float A = 1.f, B = 0.f;
    #pragma unroll 4
    for (int sl = 0; sl < CHUNK; sl++) {
        int s = j*CHUNK + sl;
        int t = dir ? (SEQ-1 - s) : s;
        size_t row = base + (size_t)t * 3072;
        float hid  = __half2float(hg[row + coff]);
        float gate = __half2float(hg[row + coff + 768]);
        float a, b;
        scan_ab(hid, gate, a, b);
        A = a * A;
        B = fmaf(a, B, b);
    }
    As[j][lane] = A;
    Bs[j][lane] = B;
    __syncthreads();

    // Phase 2: per-chain serial prefix over 8 chunks (warp 0)
    if (threadIdx.x < 32) {
        float h = 0.f;
        #pragma unroll
        for (int k = 0; k < NCHUNK; k++) {
            Hs[k][lane] = h;
            h = fmaf(As[k][lane], h, Bs[k][lane]);
        }
    }
    __syncthreads();

    // Phase 3: replay chunk from h_init, writing e
    float h = Hs[j][lane];
    #pragma unroll 4
    for (int sl = 0; sl < CHUNK; sl++) {
        int s = j*CHUNK + sl;
        int t = dir ? (SEQ-1 - s) : s;
        size_t row = base + (size_t)t * 3072;
        float hid  = __half2float(hg[row + coff]);
        float gate = __half2float(hg[row + coff + 768]);
        float a, b;
        scan_ab(hid, gate, a, b);
        h = fmaf(a, h, b);
        e[ebase + (size_t)t*1536 + eoff] = __float2half(h);
    }
}

// ---------------- launch -------------------------------------------------
extern "C" void kernel_launch(void* const* d_in, const int* in_sizes, int n_in,
                              void* d_out, int out_size)
{
    const float* x        = (const float*)d_in[0];
    const float* gamma1   = (const float*)d_in[1];
    const float* beta1    = (const float*)d_in[2];
    const float* dwc_w    = (const float*)d_in[3];
    const float* dwc_b    = (const float*)d_in[4];
    const float* gru1_w   = (const float*)d_in[5];
    const float* gru1_out = (const float*)d_in[6];
    const float* gru2_w   = (const float*)d_in[7];
    const float* gru2_out = (const float*)d_in[8];
    const float* gamma2   = (const float*)d_in[9];
    const float* beta2    = (const float*)d_in[10];
    const float* p1_w     = (const float*)d_in[11];
    const float* p1_b     = (const float*)d_in[12];
    const float* p2_w     = (const float*)d_in[13];
    const float* p2_b     = (const float*)d_in[14];
    float* out = (float*)d_out;

    float *y;
    __half *xn, *xs, *hg, *e, *yn, *yh, *wT, *oT, *p1T, *p2T;
    cudaGetSymbolAddress((void**)&xn,  g_xn);
    cudaGetSymbolAddress((void**)&xs,  g_xs);
    cudaGetSymbolAddress((void**)&hg,  g_hg);
    cudaGetSymbolAddress((void**)&e,   g_e);
    cudaGetSymbolAddress((void**)&y,   g_y);
    cudaGetSymbolAddress((void**)&yn,  g_yn);
    cudaGetSymbolAddress((void**)&yh,  g_yh);
    cudaGetSymbolAddress((void**)&wT,  g_wT);
    cudaGetSymbolAddress((void**)&oT,  g_oT);
    cudaGetSymbolAddress((void**)&p1T, g_p1T);
    cudaGetSymbolAddress((void**)&p2T, g_p2T);

    cudaFuncSetAttribute(tc_gemm<0,float>,  cudaFuncAttributeMaxDynamicSharedMemorySize, GSMEM);
    cudaFuncSetAttribute(tc_gemm<0,__half>, cudaFuncAttributeMaxDynamicSharedMemorySize, GSMEM);
    cudaFuncSetAttribute(tc_gemm<1,__half>, cudaFuncAttributeMaxDynamicSharedMemorySize, GSMEM);

    // 0. all weight transposes in one launch (K-major fp16 B operands)
    {
        TransParams tp;
        tp.in[0]=gru1_w;   tp.out[0]=wT;                      tp.K[0]=DIMC; tp.N[0]=2*DIC; tp.ostr[0]=DIMC;
        tp.in[1]=gru2_w;   tp.out[1]=wT+(size_t)1536*DIMC;    tp.K[1]=DIMC; tp.N[1]=2*DIC; tp.ostr[1]=DIMC;
        tp.in[2]=gru1_out; tp.out[2]=oT;                      tp.K[2]=DIC;  tp.N[2]=DIMC;  tp.ostr[2]=1536;
        tp.in[3]=gru2_out; tp.out[3]=oT+768;                  tp.K[3]=DIC;  tp.N[3]=DIMC;  tp.ostr[3]=1536;
        tp.in[4]=p1_w;     tp.out[4]=p1T;                     tp.K[4]=DIMC; tp.N[4]=MLPD;  tp.ostr[4]=DIMC;
        tp.in[5]=p2_w;     tp.out[5]=p2T;                     tp.K[5]=MLPD; tp.N[5]=DIMC;  tp.ostr[5]=MLPD;
        transpose_all_kernel<<<dim3(48, 48, 6), 256>>>(tp);
    }
    // 1. LN1 (fp16 out -> conv input)
    ln_kernel<__half><<<(TOK*32 + 255)/256, 256>>>(x, gamma1, beta1, xn, TOK);
    // 2. depthwise conv 3x3 (fp16 in/out, 4 ch/thread)
    dwconv_kernel<<<(TOK*(DIMC/4) + 255)/256, 256>>>(xn, dwc_w, dwc_b, xs);
    // 3. fused GRU input projections: hg = xs @ [W1|W2]  (N=3072, K=384), fp16 out
    tc_gemm<0,__half><<<dim3(3072/64, TOK/128), 128, GSMEM>>>(
        xs, wT, nullptr, nullptr, hg, TOK, 3072, DIMC);
    // 4. chunked affine minGRU scans (8x time-parallel) -> e[tok][1536]
    scan_kernel<<<2*NB*(DIC/32), 256>>>(hg, e);
    // 5. fused output projections + residual: y = e @ [O1;O2] + x  (K=1536), f32
    tc_gemm<0,float><<<dim3(DIMC/64, TOK/128), 128, GSMEM>>>(
        e, oT, nullptr, x, y, TOK, DIMC, 1536);
    // 6. LN2 (fp16 out)
    ln_kernel<__half><<<(TOK*32 + 255)/256, 256>>>(y, gamma2, beta2, yn, TOK);
    // 7. MLP up + exact GELU (fp16 out)
    tc_gemm<1,__half><<<dim3(MLPD/64, TOK/128), 128, GSMEM>>>(
        yn, p1T, p1_b, nullptr, yh, TOK, MLPD, DIMC);
    // 8. MLP down + bias + residual -> out (f32)
    tc_gemm<0,float><<<dim3(DIMC/64, TOK/128), 128, GSMEM>>>(
        yh, p2T, p2_b, y, out, TOK, DIMC, MLPD);
}